// round 16
// baseline (speedup 1.0000x reference)
#include <cuda_runtime.h>
#include <cuda_bf16.h>
#include <cstdint>

#define NN 3072
#define PP 4
#define FF 64
#define INF_ 256
#define LALPHA 0.2f
#define NSPLIT 3
#define JT3 (NN / NSPLIT)          // 1024
#define NCHUNK (JT3 / 64)          // 16

// dynamic smem layout for k_pass2p (3-stage ring)
#define SM_BS   0                  // bf16 bs[3][2][64*64]   : 49152 B (16384/stage: hi 8K + lo 8K)
#define SM_ES   49152              // float es[3][64][72]    : 55296 B (18432/stage)
#define SM_VS   104448             // float v_s[JT3]         : 4096 B
#define SM_RED1 108544             // float red1[128]        : 512 B
#define SM_RED2 109056             // float red2[128]        : 512 B
#define SM_TOT  109568

// ---------------- device scratch ----------------
__device__ float g_Wh[NN * FF];
__device__ float g_s1[NN];
__device__ float g_s2[NN];
__device__ float g_rs[PP * NN];
__device__ float g_cs[PP * NN];
__device__ __nv_bfloat16 g_whT_h[FF * NN];   // Wh^T bf16 hi [f][j]
__device__ __nv_bfloat16 g_whT_l[FF * NN];   // residual lo
__device__ float g_part[NSPLIT][NN * PP * FF];
__device__ float g_e[(size_t)PP * NN * NN];  // fallback e storage

__device__ __forceinline__ uint32_t smem_u32(const void* p) {
    uint32_t a;
    asm("{ .reg .u64 t; cvta.to.shared.u64 t, %1; cvt.u32.u64 %0, t; }" : "=r"(a) : "l"(p));
    return a;
}
__device__ __forceinline__ uint32_t swz(uint32_t o) { return o ^ ((o >> 3) & 0x70); }
__device__ __forceinline__ void cp_async16(uint32_t dst, const void* src) {
    asm volatile("cp.async.cg.shared.global [%0], [%1], 16;" :: "r"(dst), "l"(src) : "memory");
}
#define CP_COMMIT() asm volatile("cp.async.commit_group;" ::: "memory")
#define CP_WAIT(N)  asm volatile("cp.async.wait_group %0;" :: "n"(N) : "memory")
__device__ __forceinline__ void ldsm4(uint32_t& r0, uint32_t& r1, uint32_t& r2, uint32_t& r3,
                                      uint32_t addr) {
    asm volatile("ldmatrix.sync.aligned.m8n8.x4.shared.b16 {%0,%1,%2,%3}, [%4];"
                 : "=r"(r0), "=r"(r1), "=r"(r2), "=r"(r3) : "r"(addr));
}
#define MMA(c, a0, a1, a2, a3, b0, b1) \
    asm volatile("mma.sync.aligned.m16n8k16.row.col.f32.bf16.bf16.f32 " \
        "{%0,%1,%2,%3}, {%4,%5,%6,%7}, {%8,%9}, {%0,%1,%2,%3};" \
        : "+f"((c)[0]), "+f"((c)[1]), "+f"((c)[2]), "+f"((c)[3]) \
        : "r"(a0), "r"(a1), "r"(a2), "r"(a3), "r"(b0), "r"(b1))

// ---------------- kernel A: Wh = h @ W (+ splits, s1/s2, zero reductions) ----------------
__global__ void __launch_bounds__(256) k_wh(const float* __restrict__ h,
                                            const float* __restrict__ W,
                                            const float* __restrict__ a) {
    __shared__ float hs[32][INF_];
    __shared__ float red[8][8][2];
    int i0 = blockIdx.x * 32;
    int tid = threadIdx.x;
    if (blockIdx.x < 48) {
        int z = blockIdx.x * 256 + tid;
        g_rs[z] = 0.f; g_cs[z] = 0.f;
    }
    const float4* hg = (const float4*)(h + (size_t)i0 * INF_);
    float4* hs4 = (float4*)hs;
#pragma unroll
    for (int k = 0; k < 8; k++) hs4[tid + 256 * k] = hg[tid + 256 * k];
    __syncthreads();
    int f = tid & 63, ir = tid >> 6, lane = tid & 31, wrp = tid >> 5;
    float acc[8];
#pragma unroll
    for (int r = 0; r < 8; r++) acc[r] = 0.f;
    for (int k = 0; k < INF_; k++) {
        float wk = W[k * FF + f];
#pragma unroll
        for (int r = 0; r < 8; r++) acc[r] += hs[ir * 8 + r][k] * wk;
    }
    float a1 = a[f], a2 = a[FF + f];
#pragma unroll
    for (int r = 0; r < 8; r++) {
        int i = i0 + ir * 8 + r;
        g_Wh[(size_t)i * FF + f] = acc[r];
        __nv_bfloat16 hb = __float2bfloat16(acc[r]);
        g_whT_h[(size_t)f * NN + i] = hb;
        g_whT_l[(size_t)f * NN + i] = __float2bfloat16(acc[r] - __bfloat162float(hb));
        float p1 = acc[r] * a1, p2 = acc[r] * a2;
#pragma unroll
        for (int o = 16; o > 0; o >>= 1) {
            p1 += __shfl_down_sync(0xffffffffu, p1, o);
            p2 += __shfl_down_sync(0xffffffffu, p2, o);
        }
        if (lane == 0) { red[wrp][r][0] = p1; red[wrp][r][1] = p2; }
    }
    __syncthreads();
    if (tid < 32) {
        int irr = tid >> 3, r = tid & 7;
        g_s1[i0 + irr * 8 + r] = red[2 * irr][r][0] + red[2 * irr + 1][r][0];
        g_s2[i0 + irr * 8 + r] = red[2 * irr][r][1] + red[2 * irr + 1][r][1];
    }
}

// ---------------- kernel C: e + row/col sums (row-reduce hoisted out of loop) ----------------
__global__ void __launch_bounds__(256) k_pass1(const float* __restrict__ edge,
                                               float* __restrict__ e_out) {
    int p = blockIdx.y;
    int i0 = blockIdx.x * 16;
    int tid = threadIdx.x;
    const float4* s2v = (const float4*)g_s2;
    float4 s2r[3];
#pragma unroll
    for (int k = 0; k < 3; k++) s2r[k] = s2v[tid + 256 * k];
    float4 ca[3];
#pragma unroll
    for (int k = 0; k < 3; k++) ca[k] = make_float4(0.f, 0.f, 0.f, 0.f);
    float rsum[16];
#pragma unroll
    for (int r = 0; r < 16; r++) rsum[r] = 0.f;

    const float4* eg = (const float4*)(edge + (size_t)p * NN * NN);
    float4* eo = (float4*)(e_out + (size_t)p * NN * NN);

#pragma unroll 2
    for (int r = 0; r < 16; r++) {
        int i = i0 + r;
        float s1i = g_s1[i];
        size_t rb = (size_t)i * (NN / 4);
        float rp = 0.f;
#pragma unroll
        for (int k = 0; k < 3; k++) {
            float4 ea = eg[rb + tid + 256 * k];
            float4 s2q = s2r[k];
            float4 ev; float x;
            x = s1i + s2q.x; x = x > 0.f ? x : LALPHA * x; ev.x = x * ea.x;
            x = s1i + s2q.y; x = x > 0.f ? x : LALPHA * x; ev.y = x * ea.y;
            x = s1i + s2q.z; x = x > 0.f ? x : LALPHA * x; ev.z = x * ea.z;
            x = s1i + s2q.w; x = x > 0.f ? x : LALPHA * x; ev.w = x * ea.w;
            eo[rb + tid + 256 * k] = ev;
            rp += (ev.x + ev.y) + (ev.z + ev.w);
            ca[k].x += ev.x; ca[k].y += ev.y; ca[k].z += ev.z; ca[k].w += ev.w;
        }
        rsum[r] = rp;
    }
    // row reductions hoisted: no shfl chains in the streaming loop
#pragma unroll
    for (int r = 0; r < 16; r++) {
        float rp = rsum[r];
#pragma unroll
        for (int o = 16; o > 0; o >>= 1) rp += __shfl_down_sync(0xffffffffu, rp, o);
        if ((tid & 31) == 0) atomicAdd(&g_rs[p * NN + i0 + r], rp);
    }
#pragma unroll
    for (int k = 0; k < 3; k++) {
        int j = (tid + 256 * k) * 4;
        atomicAdd(&g_cs[p * NN + j + 0], ca[k].x);
        atomicAdd(&g_cs[p * NN + j + 1], ca[k].y);
        atomicAdd(&g_cs[p * NN + j + 2], ca[k].z);
        atomicAdd(&g_cs[p * NN + j + 3], ca[k].w);
    }
}

// ---------------- kernel E: 3-stage cp.async pipeline, mma.sync GEMM, j-split x3 ----------------
// grid (48, 4, 3), 128 threads = 4 warps; inline scalar reduction; dynamic smem SM_TOT.
__global__ void __launch_bounds__(128) k_pass2p(const float* __restrict__ e_in,
                                                float* __restrict__ part) {
    extern __shared__ __align__(16) char smem[];
    float* v_s  = (float*)(smem + SM_VS);
    float* red1 = (float*)(smem + SM_RED1);
    float* red2 = (float*)(smem + SM_RED2);

    int tid = threadIdx.x, lane = tid & 31, w = tid >> 5;
    int p = blockIdx.y, i0 = blockIdx.x * 64;
    int third = blockIdx.z;
    int j0 = third * JT3;

    int g = lane >> 2, q = (lane & 3) * 2;
    int r0 = w * 16 + g, r1 = r0 + 8;
    int row0 = i0 + r0;

    int brow = (lane & 7) + ((lane >> 1) & 8);
    int bk = ((lane >> 3) & 1) * 8;
    uint32_t sb = smem_u32(smem);
    const float* egbase = e_in + (size_t)p * NN * NN + (size_t)i0 * NN + j0;

#define STAGE(cc) do { \
    int st_ = (cc) % 3; \
    uint32_t stB = sb + (uint32_t)st_ * 16384u; \
    uint32_t stE = sb + SM_ES + (uint32_t)st_ * 18432u; \
    _Pragma("unroll") \
    for (int t = 0; t < 4; t++) { \
        int s = tid + t * 128; \
        int fr = s >> 3, col = s & 7; \
        uint32_t o = swz((uint32_t)(fr * 128 + col * 16)); \
        cp_async16(stB + o,        g_whT_h + (size_t)fr * NN + j0 + (cc) * 64 + col * 8); \
        cp_async16(stB + 8192 + o, g_whT_l + (size_t)fr * NN + j0 + (cc) * 64 + col * 8); \
    } \
    _Pragma("unroll") \
    for (int t = 0; t < 8; t++) { \
        int s = tid + t * 128; \
        int row = s >> 4, c = s & 15; \
        cp_async16(stE + (uint32_t)((row * 72 + c * 4) * 4), \
                   egbase + (size_t)row * NN + (cc) * 64 + c * 4); \
    } \
    CP_COMMIT(); \
} while (0)

    STAGE(NCHUNK - 1);   // overlap first prefetch with the scalar reduction below

    // ---- inline scalar reduction: lamb = max(rs,cs), r = N*lamb - sum(rs) ----
    {
        float mx = -1e30f, sm = 0.f;
#pragma unroll
        for (int k = tid; k < NN; k += 128) {
            float rv = g_rs[p * NN + k];
            float cv = g_cs[p * NN + k];
            mx = fmaxf(mx, fmaxf(rv, cv));
            sm += rv;
        }
        red1[tid] = mx; red2[tid] = sm;
        __syncthreads();
        for (int s = 64; s > 0; s >>= 1) {
            if (tid < s) { red1[tid] = fmaxf(red1[tid], red1[tid + s]); red2[tid] += red2[tid + s]; }
            __syncthreads();
        }
    }
    float lamb = red1[0];
    float inv_r = 1.f / ((float)NN * lamb - red2[0]);
    float inv_l = 1.f / lamb;   // analytic: col-normalizer == lamb

    float u0 = (lamb - g_rs[p * NN + row0]) * inv_r;
    float u1 = (lamb - g_rs[p * NN + row0 + 8]) * inv_r;

    STAGE(NCHUNK - 2);   // second stage in flight before the mainloop

#pragma unroll
    for (int t = tid; t < JT3; t += 128)
        v_s[t] = (lamb - g_cs[p * NN + j0 + t]) * inv_l;

    float cacc[8][4];
#pragma unroll
    for (int n = 0; n < 8; n++)
#pragma unroll
        for (int r = 0; r < 4; r++) cacc[n][r] = 0.f;

    // reverse order: read e newest-first (freshest in L2); 2 chunks always in flight
    for (int ch = NCHUNK - 1; ch >= 0; ch--) {
        if (ch > 1)      { STAGE(ch - 2); CP_WAIT(2); }
        else if (ch == 1){ CP_WAIT(1); }
        else             { CP_WAIT(0); }
        __syncthreads();

        int st = ch % 3;
        uint32_t sbase = sb + (uint32_t)st * 16384u;
        const float* esp = (const float*)(smem + SM_ES + st * 18432);
#pragma unroll
        for (int ks = 0; ks < 4; ks++) {
            int kb = ch * 64 + ks * 16;
            int kl = ks * 16;
            float2 e00 = *(const float2*)&esp[r0 * 72 + kl + q];
            float2 e10 = *(const float2*)&esp[r1 * 72 + kl + q];
            float2 e01 = *(const float2*)&esp[r0 * 72 + kl + q + 8];
            float2 e11 = *(const float2*)&esp[r1 * 72 + kl + q + 8];
            float2 vA = *(const float2*)&v_s[kb + q];
            float2 vB = *(const float2*)&v_s[kb + q + 8];
            float a00 = e00.x > 0.f ? fmaf(u0, vA.x, e00.x * inv_l) : e00.x;
            float a01 = e00.y > 0.f ? fmaf(u0, vA.y, e00.y * inv_l) : e00.y;
            float a10 = e10.x > 0.f ? fmaf(u1, vA.x, e10.x * inv_l) : e10.x;
            float a11 = e10.y > 0.f ? fmaf(u1, vA.y, e10.y * inv_l) : e10.y;
            float a02 = e01.x > 0.f ? fmaf(u0, vB.x, e01.x * inv_l) : e01.x;
            float a03 = e01.y > 0.f ? fmaf(u0, vB.y, e01.y * inv_l) : e01.y;
            float a12 = e11.x > 0.f ? fmaf(u1, vB.x, e11.x * inv_l) : e11.x;
            float a13 = e11.y > 0.f ? fmaf(u1, vB.y, e11.y * inv_l) : e11.y;
            uint32_t ah0, ah1, ah2, ah3, al0, al1, al2, al3;
            asm("cvt.rn.bf16x2.f32 %0, %1, %2;" : "=r"(ah0) : "f"(a01), "f"(a00));
            asm("cvt.rn.bf16x2.f32 %0, %1, %2;" : "=r"(ah1) : "f"(a11), "f"(a10));
            asm("cvt.rn.bf16x2.f32 %0, %1, %2;" : "=r"(ah2) : "f"(a03), "f"(a02));
            asm("cvt.rn.bf16x2.f32 %0, %1, %2;" : "=r"(ah3) : "f"(a13), "f"(a12));
            float r00 = a00 - __uint_as_float(ah0 << 16);
            float r01 = a01 - __uint_as_float(ah0 & 0xffff0000u);
            float r10 = a10 - __uint_as_float(ah1 << 16);
            float r11 = a11 - __uint_as_float(ah1 & 0xffff0000u);
            float r02 = a02 - __uint_as_float(ah2 << 16);
            float r03 = a03 - __uint_as_float(ah2 & 0xffff0000u);
            float r12 = a12 - __uint_as_float(ah3 << 16);
            float r13 = a13 - __uint_as_float(ah3 & 0xffff0000u);
            asm("cvt.rn.bf16x2.f32 %0, %1, %2;" : "=r"(al0) : "f"(r01), "f"(r00));
            asm("cvt.rn.bf16x2.f32 %0, %1, %2;" : "=r"(al1) : "f"(r11), "f"(r10));
            asm("cvt.rn.bf16x2.f32 %0, %1, %2;" : "=r"(al2) : "f"(r03), "f"(r02));
            asm("cvt.rn.bf16x2.f32 %0, %1, %2;" : "=r"(al3) : "f"(r13), "f"(r12));

            uint32_t lof = (uint32_t)(brow * 128 + (ks * 16 + bk) * 2);
#pragma unroll
            for (int np = 0; np < 4; np++) {
                uint32_t off = swz(lof + np * 2048);
                uint32_t bh0, bh1, bh2, bh3, bl0, bl1, bl2, bl3;
                ldsm4(bh0, bh1, bh2, bh3, sbase + off);
                ldsm4(bl0, bl1, bl2, bl3, sbase + 8192 + off);
                MMA(cacc[2 * np],     ah0, ah1, ah2, ah3, bh0, bh1);
                MMA(cacc[2 * np],     al0, al1, al2, al3, bh0, bh1);
                MMA(cacc[2 * np],     ah0, ah1, ah2, ah3, bl0, bl1);
                MMA(cacc[2 * np + 1], ah0, ah1, ah2, ah3, bh2, bh3);
                MMA(cacc[2 * np + 1], al0, al1, al2, al3, bh2, bh3);
                MMA(cacc[2 * np + 1], ah0, ah1, ah2, ah3, bl2, bl3);
            }
        }
        __syncthreads();
    }

    // ---- store partials ----
    float* o0 = part + (size_t)third * (NN * PP * FF)
              + (size_t)row0 * (PP * FF) + p * FF + q;
    float* o1 = o0 + (size_t)8 * (PP * FF);
#pragma unroll
    for (int n = 0; n < 8; n++) {
        *(float2*)(o0 + n * 8) = make_float2(cacc[n][0], cacc[n][1]);
        *(float2*)(o1 + n * 8) = make_float2(cacc[n][2], cacc[n][3]);
    }
#undef STAGE
}

// ---------------- kernel F: combine thirds + elu ----------------
__global__ void __launch_bounds__(256) k_elu(const float* __restrict__ part,
                                             float* __restrict__ out0) {
    int i = blockIdx.x * 256 + threadIdx.x;
    float4 a = ((const float4*)part)[i];
    float4 b = ((const float4*)(part + (size_t)NN * PP * FF))[i];
    float4 c = ((const float4*)(part + (size_t)2 * NN * PP * FF))[i];
    float4 v;
    v.x = a.x + b.x + c.x; v.y = a.y + b.y + c.y;
    v.z = a.z + b.z + c.z; v.w = a.w + b.w + c.w;
    v.x = v.x > 0.f ? v.x : expm1f(v.x);
    v.y = v.y > 0.f ? v.y : expm1f(v.y);
    v.z = v.z > 0.f ? v.z : expm1f(v.z);
    v.w = v.w > 0.f ? v.w : expm1f(v.w);
    ((float4*)out0)[i] = v;
}

// ---------------- launch ----------------
extern "C" void kernel_launch(void* const* d_in, const int* in_sizes, int n_in,
                              void* d_out, int out_size) {
    const float* h    = (const float*)d_in[0];
    const float* edge = (const float*)d_in[1];
    const float* W    = (const float*)d_in[2];
    const float* a    = (const float*)d_in[3];
    float* out = (float*)d_out;

    float* e_dst;
    long long need = (long long)NN * PP * FF + (long long)PP * NN * NN;
    if ((long long)out_size >= need) {
        e_dst = out + (size_t)NN * PP * FF;
    } else {
        void* pe = nullptr;
        cudaGetSymbolAddress(&pe, g_e);
        e_dst = (float*)pe;
    }
    void* ppart = nullptr;
    cudaGetSymbolAddress(&ppart, g_part);
    float* part = (float*)ppart;

    static bool attr_done = false;
    if (!attr_done) {
        cudaFuncSetAttribute(k_pass2p, cudaFuncAttributeMaxDynamicSharedMemorySize, SM_TOT);
        attr_done = true;
    }

    k_wh<<<NN / 32, 256>>>(h, W, a);
    k_pass1<<<dim3(NN / 16, PP), 256>>>(edge, e_dst);
    k_pass2p<<<dim3(NN / 64, PP, NSPLIT), 128, SM_TOT>>>(e_dst, part);
    k_elu<<<(NN * PP * FF / 4 + 255) / 256, 256>>>(part, out);
}

// round 17
// speedup vs baseline: 1.0199x; 1.0199x over previous
#include <cuda_runtime.h>
#include <cuda_bf16.h>
#include <cstdint>

#define NN 3072
#define PP 4
#define FF 64
#define INF_ 256
#define LALPHA 0.2f
#define NSPLIT 3
#define JT3 (NN / NSPLIT)          // 1024
#define NCHUNK (JT3 / 64)          // 16

// dynamic smem layout for k_pass2p (256 threads, 128-row tile, 2-stage ring)
#define SM_BS   0                  // bf16 bs[2][2][64*64]   : 32768 B (16384/stage: hi 8K + lo 8K)
#define SM_ES   32768              // float es[2][128][72]   : 73728 B (36864/stage)
#define SM_VS   106496             // float v_s[JT3]         : 4096 B
#define SM_RED1 110592             // float red1[256]        : 1024 B
#define SM_RED2 111616             // float red2[256]        : 1024 B
#define SM_TOT  112640

// ---------------- device scratch ----------------
__device__ float g_Wh[NN * FF];
__device__ float g_s1[NN];
__device__ float g_s2[NN];
__device__ float g_rs[PP * NN];
__device__ float g_cs[PP * NN];
__device__ __nv_bfloat16 g_whT_h[FF * NN];   // Wh^T bf16 hi [f][j]
__device__ __nv_bfloat16 g_whT_l[FF * NN];   // residual lo
__device__ float g_part[NSPLIT][NN * PP * FF];
__device__ float g_e[(size_t)PP * NN * NN];  // fallback e storage

__device__ __forceinline__ uint32_t smem_u32(const void* p) {
    uint32_t a;
    asm("{ .reg .u64 t; cvta.to.shared.u64 t, %1; cvt.u32.u64 %0, t; }" : "=r"(a) : "l"(p));
    return a;
}
__device__ __forceinline__ uint32_t swz(uint32_t o) { return o ^ ((o >> 3) & 0x70); }
__device__ __forceinline__ void cp_async16(uint32_t dst, const void* src) {
    asm volatile("cp.async.cg.shared.global [%0], [%1], 16;" :: "r"(dst), "l"(src) : "memory");
}
#define CP_COMMIT() asm volatile("cp.async.commit_group;" ::: "memory")
#define CP_WAIT(N)  asm volatile("cp.async.wait_group %0;" :: "n"(N) : "memory")
__device__ __forceinline__ void ldsm4(uint32_t& r0, uint32_t& r1, uint32_t& r2, uint32_t& r3,
                                      uint32_t addr) {
    asm volatile("ldmatrix.sync.aligned.m8n8.x4.shared.b16 {%0,%1,%2,%3}, [%4];"
                 : "=r"(r0), "=r"(r1), "=r"(r2), "=r"(r3) : "r"(addr));
}
#define MMA(c, a0, a1, a2, a3, b0, b1) \
    asm volatile("mma.sync.aligned.m16n8k16.row.col.f32.bf16.bf16.f32 " \
        "{%0,%1,%2,%3}, {%4,%5,%6,%7}, {%8,%9}, {%0,%1,%2,%3};" \
        : "+f"((c)[0]), "+f"((c)[1]), "+f"((c)[2]), "+f"((c)[3]) \
        : "r"(a0), "r"(a1), "r"(a2), "r"(a3), "r"(b0), "r"(b1))

// ---------------- kernel A: Wh = h @ W (+ splits, s1/s2, zero reductions) ----------------
__global__ void __launch_bounds__(256) k_wh(const float* __restrict__ h,
                                            const float* __restrict__ W,
                                            const float* __restrict__ a) {
    __shared__ float hs[32][INF_];
    __shared__ float red[8][8][2];
    int i0 = blockIdx.x * 32;
    int tid = threadIdx.x;
    if (blockIdx.x < 48) {
        int z = blockIdx.x * 256 + tid;
        g_rs[z] = 0.f; g_cs[z] = 0.f;
    }
    const float4* hg = (const float4*)(h + (size_t)i0 * INF_);
    float4* hs4 = (float4*)hs;
#pragma unroll
    for (int k = 0; k < 8; k++) hs4[tid + 256 * k] = hg[tid + 256 * k];
    __syncthreads();
    int f = tid & 63, ir = tid >> 6, lane = tid & 31, wrp = tid >> 5;
    float acc[8];
#pragma unroll
    for (int r = 0; r < 8; r++) acc[r] = 0.f;
    for (int k = 0; k < INF_; k++) {
        float wk = W[k * FF + f];
#pragma unroll
        for (int r = 0; r < 8; r++) acc[r] += hs[ir * 8 + r][k] * wk;
    }
    float a1 = a[f], a2 = a[FF + f];
#pragma unroll
    for (int r = 0; r < 8; r++) {
        int i = i0 + ir * 8 + r;
        g_Wh[(size_t)i * FF + f] = acc[r];
        __nv_bfloat16 hb = __float2bfloat16(acc[r]);
        g_whT_h[(size_t)f * NN + i] = hb;
        g_whT_l[(size_t)f * NN + i] = __float2bfloat16(acc[r] - __bfloat162float(hb));
        float p1 = acc[r] * a1, p2 = acc[r] * a2;
#pragma unroll
        for (int o = 16; o > 0; o >>= 1) {
            p1 += __shfl_down_sync(0xffffffffu, p1, o);
            p2 += __shfl_down_sync(0xffffffffu, p2, o);
        }
        if (lane == 0) { red[wrp][r][0] = p1; red[wrp][r][1] = p2; }
    }
    __syncthreads();
    if (tid < 32) {
        int irr = tid >> 3, r = tid & 7;
        g_s1[i0 + irr * 8 + r] = red[2 * irr][r][0] + red[2 * irr + 1][r][0];
        g_s2[i0 + irr * 8 + r] = red[2 * irr][r][1] + red[2 * irr + 1][r][1];
    }
}

// ---------------- kernel C: e + row/col sums (row-reduce hoisted out of loop) ----------------
__global__ void __launch_bounds__(256) k_pass1(const float* __restrict__ edge,
                                               float* __restrict__ e_out) {
    int p = blockIdx.y;
    int i0 = blockIdx.x * 16;
    int tid = threadIdx.x;
    const float4* s2v = (const float4*)g_s2;
    float4 s2r[3];
#pragma unroll
    for (int k = 0; k < 3; k++) s2r[k] = s2v[tid + 256 * k];
    float4 ca[3];
#pragma unroll
    for (int k = 0; k < 3; k++) ca[k] = make_float4(0.f, 0.f, 0.f, 0.f);
    float rsum[16];
#pragma unroll
    for (int r = 0; r < 16; r++) rsum[r] = 0.f;

    const float4* eg = (const float4*)(edge + (size_t)p * NN * NN);
    float4* eo = (float4*)(e_out + (size_t)p * NN * NN);

#pragma unroll 2
    for (int r = 0; r < 16; r++) {
        int i = i0 + r;
        float s1i = g_s1[i];
        size_t rb = (size_t)i * (NN / 4);
        float rp = 0.f;
#pragma unroll
        for (int k = 0; k < 3; k++) {
            float4 ea = eg[rb + tid + 256 * k];
            float4 s2q = s2r[k];
            float4 ev; float x;
            x = s1i + s2q.x; x = x > 0.f ? x : LALPHA * x; ev.x = x * ea.x;
            x = s1i + s2q.y; x = x > 0.f ? x : LALPHA * x; ev.y = x * ea.y;
            x = s1i + s2q.z; x = x > 0.f ? x : LALPHA * x; ev.z = x * ea.z;
            x = s1i + s2q.w; x = x > 0.f ? x : LALPHA * x; ev.w = x * ea.w;
            eo[rb + tid + 256 * k] = ev;
            rp += (ev.x + ev.y) + (ev.z + ev.w);
            ca[k].x += ev.x; ca[k].y += ev.y; ca[k].z += ev.z; ca[k].w += ev.w;
        }
        rsum[r] = rp;
    }
    // row reductions hoisted: no shfl chains in the streaming loop
#pragma unroll
    for (int r = 0; r < 16; r++) {
        float rp = rsum[r];
#pragma unroll
        for (int o = 16; o > 0; o >>= 1) rp += __shfl_down_sync(0xffffffffu, rp, o);
        if ((tid & 31) == 0) atomicAdd(&g_rs[p * NN + i0 + r], rp);
    }
#pragma unroll
    for (int k = 0; k < 3; k++) {
        int j = (tid + 256 * k) * 4;
        atomicAdd(&g_cs[p * NN + j + 0], ca[k].x);
        atomicAdd(&g_cs[p * NN + j + 1], ca[k].y);
        atomicAdd(&g_cs[p * NN + j + 2], ca[k].z);
        atomicAdd(&g_cs[p * NN + j + 3], ca[k].w);
    }
}

// ---------------- kernel E: 256-thread, 128-row tile, 2-stage cp.async, mma.sync GEMM ----------------
// grid (24, 4, 3), 256 threads = 8 warps; warp w -> local rows [w*16, w*16+16)
__global__ void __launch_bounds__(256) k_pass2p(const float* __restrict__ e_in,
                                                float* __restrict__ part) {
    extern __shared__ __align__(16) char smem[];
    float* v_s  = (float*)(smem + SM_VS);
    float* red1 = (float*)(smem + SM_RED1);
    float* red2 = (float*)(smem + SM_RED2);

    int tid = threadIdx.x, lane = tid & 31, w = tid >> 5;
    int p = blockIdx.y, i0 = blockIdx.x * 128;
    int third = blockIdx.z;
    int j0 = third * JT3;

    int g = lane >> 2, q = (lane & 3) * 2;
    int r0 = w * 16 + g, r1 = r0 + 8;        // local rows 0..127
    int row0 = i0 + r0;

    int brow = (lane & 7) + ((lane >> 1) & 8);
    int bk = ((lane >> 3) & 1) * 8;
    uint32_t sb = smem_u32(smem);
    const float* egbase = e_in + (size_t)p * NN * NN + (size_t)i0 * NN + j0;

#define STAGE(cc) do { \
    int st_ = (cc) & 1; \
    uint32_t stB = sb + (uint32_t)st_ * 16384u; \
    uint32_t stE = sb + SM_ES + (uint32_t)st_ * 36864u; \
    _Pragma("unroll") \
    for (int t = 0; t < 2; t++) { \
        int s = tid + t * 256; \
        int fr = s >> 3, col = s & 7; \
        uint32_t o = swz((uint32_t)(fr * 128 + col * 16)); \
        cp_async16(stB + o,        g_whT_h + (size_t)fr * NN + j0 + (cc) * 64 + col * 8); \
        cp_async16(stB + 8192 + o, g_whT_l + (size_t)fr * NN + j0 + (cc) * 64 + col * 8); \
    } \
    _Pragma("unroll") \
    for (int t = 0; t < 8; t++) { \
        int s = tid + t * 256; \
        int row = s >> 4, c = s & 15; \
        cp_async16(stE + (uint32_t)((row * 72 + c * 4) * 4), \
                   egbase + (size_t)row * NN + (cc) * 64 + c * 4); \
    } \
    CP_COMMIT(); \
} while (0)

    STAGE(NCHUNK - 1);   // overlap first prefetch with the scalar reduction below

    // ---- inline scalar reduction: lamb = max(rs,cs), r = N*lamb - sum(rs) ----
    {
        float mx = -1e30f, sm = 0.f;
#pragma unroll
        for (int k = tid; k < NN; k += 256) {
            float rv = g_rs[p * NN + k];
            float cv = g_cs[p * NN + k];
            mx = fmaxf(mx, fmaxf(rv, cv));
            sm += rv;
        }
        red1[tid] = mx; red2[tid] = sm;
        __syncthreads();
        for (int s = 128; s > 0; s >>= 1) {
            if (tid < s) { red1[tid] = fmaxf(red1[tid], red1[tid + s]); red2[tid] += red2[tid + s]; }
            __syncthreads();
        }
    }
    float lamb = red1[0];
    float inv_r = 1.f / ((float)NN * lamb - red2[0]);
    float inv_l = 1.f / lamb;   // analytic: col-normalizer == lamb

    float u0 = (lamb - g_rs[p * NN + row0]) * inv_r;
    float u1 = (lamb - g_rs[p * NN + row0 + 8]) * inv_r;

#pragma unroll
    for (int t = tid; t < JT3; t += 256)
        v_s[t] = (lamb - g_cs[p * NN + j0 + t]) * inv_l;

    float cacc[8][4];
#pragma unroll
    for (int n = 0; n < 8; n++)
#pragma unroll
        for (int r = 0; r < 4; r++) cacc[n][r] = 0.f;

    // reverse order: read e newest-first (freshest in L2)
    for (int ch = NCHUNK - 1; ch >= 0; ch--) {
        if (ch > 0) { STAGE(ch - 1); CP_WAIT(1); }
        else        { CP_WAIT(0); }
        __syncthreads();

        int st = ch & 1;
        uint32_t sbase = sb + (uint32_t)st * 16384u;
        const float* esp = (const float*)(smem + SM_ES + st * 36864);
#pragma unroll
        for (int ks = 0; ks < 4; ks++) {
            int kb = ch * 64 + ks * 16;
            int kl = ks * 16;
            float2 e00 = *(const float2*)&esp[r0 * 72 + kl + q];
            float2 e10 = *(const float2*)&esp[r1 * 72 + kl + q];
            float2 e01 = *(const float2*)&esp[r0 * 72 + kl + q + 8];
            float2 e11 = *(const float2*)&esp[r1 * 72 + kl + q + 8];
            float2 vA = *(const float2*)&v_s[kb + q];
            float2 vB = *(const float2*)&v_s[kb + q + 8];
            float a00 = e00.x > 0.f ? fmaf(u0, vA.x, e00.x * inv_l) : e00.x;
            float a01 = e00.y > 0.f ? fmaf(u0, vA.y, e00.y * inv_l) : e00.y;
            float a10 = e10.x > 0.f ? fmaf(u1, vA.x, e10.x * inv_l) : e10.x;
            float a11 = e10.y > 0.f ? fmaf(u1, vA.y, e10.y * inv_l) : e10.y;
            float a02 = e01.x > 0.f ? fmaf(u0, vB.x, e01.x * inv_l) : e01.x;
            float a03 = e01.y > 0.f ? fmaf(u0, vB.y, e01.y * inv_l) : e01.y;
            float a12 = e11.x > 0.f ? fmaf(u1, vB.x, e11.x * inv_l) : e11.x;
            float a13 = e11.y > 0.f ? fmaf(u1, vB.y, e11.y * inv_l) : e11.y;
            uint32_t ah0, ah1, ah2, ah3, al0, al1, al2, al3;
            asm("cvt.rn.bf16x2.f32 %0, %1, %2;" : "=r"(ah0) : "f"(a01), "f"(a00));
            asm("cvt.rn.bf16x2.f32 %0, %1, %2;" : "=r"(ah1) : "f"(a11), "f"(a10));
            asm("cvt.rn.bf16x2.f32 %0, %1, %2;" : "=r"(ah2) : "f"(a03), "f"(a02));
            asm("cvt.rn.bf16x2.f32 %0, %1, %2;" : "=r"(ah3) : "f"(a13), "f"(a12));
            float r00 = a00 - __uint_as_float(ah0 << 16);
            float r01 = a01 - __uint_as_float(ah0 & 0xffff0000u);
            float r10 = a10 - __uint_as_float(ah1 << 16);
            float r11 = a11 - __uint_as_float(ah1 & 0xffff0000u);
            float r02 = a02 - __uint_as_float(ah2 << 16);
            float r03 = a03 - __uint_as_float(ah2 & 0xffff0000u);
            float r12 = a12 - __uint_as_float(ah3 << 16);
            float r13 = a13 - __uint_as_float(ah3 & 0xffff0000u);
            asm("cvt.rn.bf16x2.f32 %0, %1, %2;" : "=r"(al0) : "f"(r01), "f"(r00));
            asm("cvt.rn.bf16x2.f32 %0, %1, %2;" : "=r"(al1) : "f"(r11), "f"(r10));
            asm("cvt.rn.bf16x2.f32 %0, %1, %2;" : "=r"(al2) : "f"(r03), "f"(r02));
            asm("cvt.rn.bf16x2.f32 %0, %1, %2;" : "=r"(al3) : "f"(r13), "f"(r12));

            uint32_t lof = (uint32_t)(brow * 128 + (ks * 16 + bk) * 2);
#pragma unroll
            for (int np = 0; np < 4; np++) {
                uint32_t off = swz(lof + np * 2048);
                uint32_t bh0, bh1, bh2, bh3, bl0, bl1, bl2, bl3;
                ldsm4(bh0, bh1, bh2, bh3, sbase + off);
                ldsm4(bl0, bl1, bl2, bl3, sbase + 8192 + off);
                MMA(cacc[2 * np],     ah0, ah1, ah2, ah3, bh0, bh1);
                MMA(cacc[2 * np],     al0, al1, al2, al3, bh0, bh1);
                MMA(cacc[2 * np],     ah0, ah1, ah2, ah3, bl0, bl1);
                MMA(cacc[2 * np + 1], ah0, ah1, ah2, ah3, bh2, bh3);
                MMA(cacc[2 * np + 1], al0, al1, al2, al3, bh2, bh3);
                MMA(cacc[2 * np + 1], ah0, ah1, ah2, ah3, bl2, bl3);
            }
        }
        __syncthreads();
    }

    // ---- store partials ----
    float* o0 = part + (size_t)third * (NN * PP * FF)
              + (size_t)row0 * (PP * FF) + p * FF + q;
    float* o1 = o0 + (size_t)8 * (PP * FF);
#pragma unroll
    for (int n = 0; n < 8; n++) {
        *(float2*)(o0 + n * 8) = make_float2(cacc[n][0], cacc[n][1]);
        *(float2*)(o1 + n * 8) = make_float2(cacc[n][2], cacc[n][3]);
    }
#undef STAGE
}

// ---------------- kernel F: combine thirds + elu ----------------
__global__ void __launch_bounds__(256) k_elu(const float* __restrict__ part,
                                             float* __restrict__ out0) {
    int i = blockIdx.x * 256 + threadIdx.x;
    float4 a = ((const float4*)part)[i];
    float4 b = ((const float4*)(part + (size_t)NN * PP * FF))[i];
    float4 c = ((const float4*)(part + (size_t)2 * NN * PP * FF))[i];
    float4 v;
    v.x = a.x + b.x + c.x; v.y = a.y + b.y + c.y;
    v.z = a.z + b.z + c.z; v.w = a.w + b.w + c.w;
    v.x = v.x > 0.f ? v.x : expm1f(v.x);
    v.y = v.y > 0.f ? v.y : expm1f(v.y);
    v.z = v.z > 0.f ? v.z : expm1f(v.z);
    v.w = v.w > 0.f ? v.w : expm1f(v.w);
    ((float4*)out0)[i] = v;
}

// ---------------- launch ----------------
extern "C" void kernel_launch(void* const* d_in, const int* in_sizes, int n_in,
                              void* d_out, int out_size) {
    const float* h    = (const float*)d_in[0];
    const float* edge = (const float*)d_in[1];
    const float* W    = (const float*)d_in[2];
    const float* a    = (const float*)d_in[3];
    float* out = (float*)d_out;

    float* e_dst;
    long long need = (long long)NN * PP * FF + (long long)PP * NN * NN;
    if ((long long)out_size >= need) {
        e_dst = out + (size_t)NN * PP * FF;
    } else {
        void* pe = nullptr;
        cudaGetSymbolAddress(&pe, g_e);
        e_dst = (float*)pe;
    }
    void* ppart = nullptr;
    cudaGetSymbolAddress(&ppart, g_part);
    float* part = (float*)ppart;

    static bool attr_done = false;
    if (!attr_done) {
        cudaFuncSetAttribute(k_pass2p, cudaFuncAttributeMaxDynamicSharedMemorySize, SM_TOT);
        attr_done = true;
    }

    k_wh<<<NN / 32, 256>>>(h, W, a);
    k_pass1<<<dim3(NN / 16, PP), 256>>>(edge, e_dst);
    k_pass2p<<<dim3(NN / 128, PP, NSPLIT), 256, SM_TOT>>>(e_dst, part);
    k_elu<<<(NN * PP * FF / 4 + 255) / 256, 256>>>(part, out);
}